// round 8
// baseline (speedup 1.0000x reference)
#include <cuda_runtime.h>

// Kaldi LinearResample 16000 -> 14400 (polyphase, up=9, stride=10), warp-autonomous:
// each WARP owns a 32-k-block tile with its own 2-stage cp.async ring. No block
// barriers at all -> no barrier skew, continuous DRAM request stream.
//   out[b, 9k+i] = sum_m w[i][m] * x[b, 10k + fi[i] + m]
//   121 nonzero taps baked as compile-time float literals -> FFMA-imm.

#define T_IN        480000
#define TOT_K       48000
#define UP          9
#define TOT_OUT     (TOT_K * UP)
#define WARP_K      32            // k-blocks per warp-tile
#define WT_PER_ROW  1500          // 48000 / 32
#define STAGE_V     84            // float4s staged: covers 10*31+22+shift = 334 floats
#define STAGE_F     344           // padded stage stride (floats)
#define NWARPS      8             // warps per CTA (256 threads)
#define NCTA        888           // 148 SM * 6 CTAs

// ---------------- compile-time weight table ----------------
constexpr double KPI = 3.14159265358979323846264338327950288;

constexpr double tsin(double x) {
    while (x >  KPI) x -= 2.0 * KPI;
    while (x < -KPI) x += 2.0 * KPI;
    double x2 = x * x, term = x, s = x;
    for (int k = 1; k <= 16; ++k) {
        term *= -x2 / (double)((2 * k) * (2 * k + 1));
        s += term;
    }
    return s;
}
constexpr double tcos(double x) { return tsin(KPI * 0.5 - x); }

struct WTab { float w[9][14]; };
constexpr WTab make_wtab() {
    WTab t{};
    constexpr int FI[9] = {-6, -5, -4, -3, -2, -1, 0, 2, 3};
    for (int i = 0; i < 9; ++i)
        for (int m = 0; m < 14; ++m) {
            int n = 9 * (FI[i] + m) - 10 * i;
            int an = n < 0 ? -n : n;
            double v = 0.0;
            if (an == 0)      v = 0.891;            // 2*lowpass_cutoff/orig_freq
            else if (an <= 60)
                v = (1.0 + tcos(0.0165 * KPI * an)) * tsin(0.099 * KPI * an)
                    * 9.0 / (2.0 * KPI * an);
            t.w[i][m] = (float)v;
        }
    return t;
}
__device__ constexpr WTab WT = make_wtab();

// ---------------- cp.async helpers ----------------
__device__ __forceinline__ void cp_async16(float* smem_dst, const float* gsrc) {
    unsigned saddr = (unsigned)__cvta_generic_to_shared(smem_dst);
    asm volatile("cp.async.cg.shared.global [%0], [%1], 16;" :: "r"(saddr), "l"(gsrc));
}
#define CP_COMMIT() asm volatile("cp.async.commit_group;" ::: "memory")
#define CP_WAIT1()  asm volatile("cp.async.wait_group 1;"  ::: "memory")

__device__ __forceinline__ void stg_cs16(float4* dst, float4 v) {
    asm volatile("st.global.cs.v4.f32 [%0], {%1, %2, %3, %4};"
                 :: "l"(dst), "f"(v.x), "f"(v.y), "f"(v.z), "f"(v.w) : "memory");
}

// ---------------- warp-scope staging of one 32-k tile ----------------
__device__ __forceinline__ void stage_warp(float* ws, const float* __restrict__ in,
                                           int wt, int lane) {
    const int b  = wt / WT_PER_ROW;
    const int kt = (wt - b * WT_PER_ROW) * WARP_K;
    const float* rowin = in + (size_t)b * T_IN;
    const int gstart = 10 * kt - 6;
    const int g4 = gstart & ~3;

    if (g4 >= 0 && g4 + 4 * STAGE_V <= T_IN) {
        // interior (1498 of 1500 warp-tiles per row)
#pragma unroll
        for (int v = lane; v < STAGE_V; v += 32)
            cp_async16(ws + 4 * v, rowin + g4 + 4 * v);
    } else {
        // row edge: guarded scalar path with zero padding (plain STS)
        for (int v = lane; v < STAGE_V; v += 32) {
            int g = g4 + 4 * v;
            float4 val;
            if (g >= 0 && g <= T_IN - 4) {
                val = *reinterpret_cast<const float4*>(rowin + g);
            } else {
                val.x = (g + 0 >= 0 && g + 0 < T_IN) ? rowin[g + 0] : 0.0f;
                val.y = (g + 1 >= 0 && g + 1 < T_IN) ? rowin[g + 1] : 0.0f;
                val.z = (g + 2 >= 0 && g + 2 < T_IN) ? rowin[g + 2] : 0.0f;
                val.w = (g + 3 >= 0 && g + 3 < T_IN) ? rowin[g + 3] : 0.0f;
            }
            *reinterpret_cast<float4*>(ws + 4 * v) = val;
        }
    }
}

__global__ __launch_bounds__(32 * NWARPS, 6)
void sp_resample_kernel(const float* __restrict__ in, float* __restrict__ out,
                        int nwt) {
    __shared__ float xs[NWARPS][2][STAGE_F];
    __shared__ float os[NWARPS][WARP_K * UP];   // 288 floats per warp

    const int tid  = threadIdx.x;
    const int wid  = tid >> 5;
    const int lane = tid & 31;
    const int gw      = blockIdx.x * NWARPS + wid;
    const int gstride = gridDim.x * NWARPS;

    float* ws0 = xs[wid][0];
    float* ws1 = xs[wid][1];
    float* ow  = os[wid];

    if (gw < nwt) stage_warp(ws0, in, gw, lane);
    CP_COMMIT();

    int cur = 0;
    for (int wt = gw; wt < nwt; wt += gstride) {
        const int tn = wt + gstride;
        if (tn < nwt) stage_warp(cur ? ws0 : ws1, in, tn, lane);
        CP_COMMIT();
        CP_WAIT1();                 // own cp.async for xs[cur] complete
        __syncwarp();               // cross-lane visibility (warp memory barrier)

        const int b  = wt / WT_PER_ROW;
        const int kt = (wt - b * WT_PER_ROW) * WARP_K;
        const int gstart = 10 * kt - 6;
        const int shift  = gstart & 3;                 // 0 or 2 (gstart even)
        const float* xb = cur ? ws1 : ws0;

        {
            float2 xr2[11];
            const int w0 = 10 * lane + shift;          // even -> aligned float2
#pragma unroll
            for (int c = 0; c < 11; ++c)
                xr2[c] = *reinterpret_cast<const float2*>(xb + w0 + 2 * c);
#define XR(c) (((c) & 1) ? xr2[(c) >> 1].y : xr2[(c) >> 1].x)

            constexpr int FI6[9] = {0, 1, 2, 3, 4, 5, 6, 8, 9};
            constexpr int N0[9]  = {-54, -55, -56, -57, -58, -59, -60, -52, -53};
#pragma unroll
            for (int i = 0; i < 9; ++i) {
                float acc = 0.0f;
#pragma unroll
                for (int m = 0; m < 14; ++m) {
                    const int n  = N0[i] + 9 * m;
                    const int an = (n < 0) ? -n : n;
                    if (an <= 60) {                    // pruned at compile time
                        acc = fmaf(WT.w[i][m], XR(FI6[i] + m), acc);
                    }
                }
                ow[9 * lane + i] = acc;
            }
#undef XR
        }
        __syncwarp();               // transpose buffer complete

        {
            const size_t ob = (size_t)b * TOT_OUT + (size_t)9 * kt;
            const float4* src = reinterpret_cast<const float4*>(ow);
            float4* dst = reinterpret_cast<float4*>(out + ob);
#pragma unroll
            for (int v = lane; v < 72; v += 32)        // 288 floats = 72 float4
                stg_cs16(dst + v, src[v]);
        }
        // next iteration's leading __syncwarp orders ow rewrite after these reads
        cur ^= 1;
    }
}

extern "C" void kernel_launch(void* const* d_in, const int* in_sizes, int n_in,
                              void* d_out, int out_size) {
    const float* in = (const float*)d_in[0];
    float* out = (float*)d_out;
    const int B = in_sizes[0] / T_IN;
    const int nwt = B * WT_PER_ROW;
    sp_resample_kernel<<<NCTA, 32 * NWARPS>>>(in, out, nwt);
}